// round 1
// baseline (speedup 1.0000x reference)
#include <cuda_runtime.h>
#include <math.h>

#define Bn 2
#define Tn 1536
#define Dn 1536
#define Hn 8
#define Kn 64
#define Vn 192
#define HK 512       // H*K
#define HV 1536      // H*V
#define Rn 3071      // 2T-1

// ---------------- scratch (device globals; no allocation allowed) -------------
__device__ float g_emb[(size_t)Rn * 192];
__device__ float g_gmax;
__device__ float g_rk[(size_t)Rn * HK];
__device__ float g_q[(size_t)Bn * Tn * HK];
__device__ float g_k[(size_t)Bn * Tn * HK];
__device__ float g_v[(size_t)Bn * Tn * HV];
__device__ float g_logits[(size_t)Bn * Hn * Tn * Tn];   // 151 MB
__device__ float g_att[(size_t)Bn * Tn * HV];

// ---------------- positional features ----------------------------------------
// emb[p, c], p in [0,2T-1), c in [0,192). cols 0..31 exp, 32..63 mask, 64..95 gamma
// (raw prob first, normalized by global max in pos_fin), cols 96..191 = sign*first96.
__global__ void pos_fill() {
    int idx = blockIdx.x * 256 + threadIdx.x;
    if (idx >= Rn * 96) return;
    int p = idx / 96, c = idx % 96;
    float ap = fabsf((float)(p - (Tn - 1)));
    float v;
    if (c < 32) {
        float max_range = log2f((float)Tn);
        float hl = exp2f(3.0f + (float)c * (max_range - 3.0f) / 31.0f);
        v = exp2f(-ap / hl);                       // exp(-ln2*ap/hl)
    } else if (c < 64) {
        float w = exp2f((float)(c - 32 + 1)) - 1.0f;
        v = (w > ap) ? 1.0f : 0.0f;
    } else {
        int i = c - 64;
        float mean = 48.0f * (float)(i + 1);       // linspace(T/n, T, n), step=48
        float conc = (mean / 24.0f) * (mean / 24.0f);
        float rate = mean * (1.0f / 576.0f);
        float lp = (conc - 1.0f) * logf(ap) - rate * ap
                   - (lgammaf(conc) - conc * logf(rate));
        v = expf(lp) + 1e-8f;                      // ap=0 -> logf=-inf -> exp=0  OK
    }
    g_emb[(size_t)p * 192 + c] = v;
}

__global__ void pos_max() {
    __shared__ float red[256];
    int tid = threadIdx.x;
    float m = 0.0f;
    for (int idx = tid; idx < Rn * 32; idx += 256) {
        int p = idx >> 5, i = idx & 31;
        m = fmaxf(m, g_emb[(size_t)p * 192 + 64 + i]);
    }
    red[tid] = m;
    __syncthreads();
    for (int o = 128; o > 0; o >>= 1) {
        if (tid < o) red[tid] = fmaxf(red[tid], red[tid + o]);
        __syncthreads();
    }
    if (tid == 0) g_gmax = red[0];
}

__global__ void pos_fin() {
    int idx = blockIdx.x * 256 + threadIdx.x;
    if (idx >= Rn * 96) return;
    int p = idx / 96, c = idx % 96;
    float v = g_emb[(size_t)p * 192 + c];
    if (c >= 64) {
        v = v / g_gmax;
        g_emb[(size_t)p * 192 + c] = v;
    }
    float sgn = (p < Tn - 1) ? -1.0f : ((p > Tn - 1) ? 1.0f : 0.0f);
    g_emb[(size_t)p * 192 + 96 + c] = sgn * v;
}

// ---------------- generic tiled SGEMM: C = alpha * A @ B ----------------------
// 128x128 tile, BK=8, 256 threads, 8x8 microtile, batched via (b,h) strides.
// Requires Kd % 8 == 0, N % 4 == 0, lda/ldb/ldc % 4 == 0.
__global__ __launch_bounds__(256) void sgemm_kernel(
    const float* __restrict__ A, const float* __restrict__ B, float* __restrict__ C,
    int M, int N, int Kd, int lda, int ldb, int ldc, int Hdim,
    long sAb, long sAh, long sBb, long sBh, long sCb, long sCh, float alpha)
{
    int z = blockIdx.z;
    int bb = z / Hdim, hh = z % Hdim;
    A += (size_t)bb * sAb + (size_t)hh * sAh;
    B += (size_t)bb * sBb + (size_t)hh * sBh;
    C += (size_t)bb * sCb + (size_t)hh * sCh;

    __shared__ __align__(16) float As[8][128];   // [k][m]
    __shared__ __align__(16) float Bs[8][128];   // [k][n]

    int tid = threadIdx.x;
    int bm = blockIdx.y * 128, bn = blockIdx.x * 128;
    int arow = tid >> 1, acol = (tid & 1) << 2;
    int brow = tid >> 5, bcol = (tid & 31) << 2;
    bool aval = (bm + arow) < M;
    bool bval = (bn + bcol) < N;
    const float* aptr = A + (size_t)(bm + arow) * lda + acol;
    const float* bptr = B + (size_t)brow * ldb + bn + bcol;
    int tx = tid & 15, ty = tid >> 4;

    float acc[8][8] = {};
    float4 av = make_float4(0.f, 0.f, 0.f, 0.f), bv = av;
    if (aval) av = *(const float4*)aptr;
    if (bval) bv = *(const float4*)bptr;

    for (int k0 = 0; k0 < Kd; k0 += 8) {
        As[acol + 0][arow] = av.x;
        As[acol + 1][arow] = av.y;
        As[acol + 2][arow] = av.z;
        As[acol + 3][arow] = av.w;
        *(float4*)&Bs[brow][bcol] = bv;
        __syncthreads();
        if (k0 + 8 < Kd) {                      // prefetch next K-tile
            av = make_float4(0.f, 0.f, 0.f, 0.f); bv = av;
            if (aval) av = *(const float4*)(aptr + k0 + 8);
            if (bval) bv = *(const float4*)(bptr + (size_t)(k0 + 8) * ldb);
        }
#pragma unroll
        for (int kk = 0; kk < 8; kk++) {
            float a[8], b[8];
            *(float4*)&a[0] = *(const float4*)&As[kk][ty * 8];
            *(float4*)&a[4] = *(const float4*)&As[kk][ty * 8 + 4];
            *(float4*)&b[0] = *(const float4*)&Bs[kk][tx * 8];
            *(float4*)&b[4] = *(const float4*)&Bs[kk][tx * 8 + 4];
#pragma unroll
            for (int i = 0; i < 8; i++)
#pragma unroll
                for (int j = 0; j < 8; j++)
                    acc[i][j] = fmaf(a[i], b[j], acc[i][j]);
        }
        __syncthreads();
    }

#pragma unroll
    for (int i = 0; i < 8; i++) {
        int r = bm + ty * 8 + i;
        if (r < M) {
            float* cp = C + (size_t)r * ldc + bn + tx * 8;
#pragma unroll
            for (int j = 0; j < 8; j += 4) {
                if (bn + tx * 8 + j < N) {
                    float4 o = make_float4(alpha * acc[i][j],     alpha * acc[i][j + 1],
                                           alpha * acc[i][j + 2], alpha * acc[i][j + 3]);
                    *(float4*)(cp + j) = o;
                }
            }
        }
    }
}

// ---------------- fused logits (content + relative-shifted rel) ---------------
// logits[b,h,q,j] = sum_k qs[q,k]*(k[j,k] + rk[m,k]) + c1[j] + c2[m],
// m = (T-1) + j - q. Per 64x64 tile m spans a 127-row band of rk.
__global__ __launch_bounds__(256) void logits_kernel(
    const float* __restrict__ rwb, const float* __restrict__ rrb)
{
    extern __shared__ float sm[];
    float* Qs   = sm;                  // [64][65]  (k-major: Qs[k*65+q])
    float* Ks   = Qs + 64 * 65;        // [64][65]
    float* RKs  = Ks + 64 * 65;        // [64][129] (k-major: RKs[k*129+ml])
    float* c1s  = RKs + 64 * 129;      // [64]
    float* c2s  = c1s + 64;            // [127]
    float* rwbs = c2s + 127;           // [64]
    float* rrbs = rwbs + 64;           // [64]

    int z = blockIdx.z, b = z >> 3, h = z & 7;
    int q0 = blockIdx.y * 64, j0 = blockIdx.x * 64;
    int tid = threadIdx.x;

    const float* qg = g_q + ((size_t)(b * Tn + q0)) * HK + h * Kn;
    const float* kg = g_k + ((size_t)(b * Tn + j0)) * HK + h * Kn;
    int mbase = (Tn - 1) + j0 - q0 - 63;   // always in [0, 2944]
    const float* rg = g_rk + (size_t)mbase * HK + h * Kn;

#pragma unroll
    for (int it = 0; it < 4; it++) {       // Q & K tiles: 1024 float4 each
        int idx = it * 256 + tid;
        int row = idx >> 4, c4 = (idx & 15) << 2;
        float4 qv = *(const float4*)(qg + (size_t)row * HK + c4);
        float4 kv = *(const float4*)(kg + (size_t)row * HK + c4);
        Qs[(c4 + 0) * 65 + row] = qv.x; Qs[(c4 + 1) * 65 + row] = qv.y;
        Qs[(c4 + 2) * 65 + row] = qv.z; Qs[(c4 + 3) * 65 + row] = qv.w;
        Ks[(c4 + 0) * 65 + row] = kv.x; Ks[(c4 + 1) * 65 + row] = kv.y;
        Ks[(c4 + 2) * 65 + row] = kv.z; Ks[(c4 + 3) * 65 + row] = kv.w;
    }
#pragma unroll
    for (int it = 0; it < 8; it++) {       // RK band: 127 rows -> 2032 float4
        int idx = it * 256 + tid;
        if (idx < 127 * 16) {
            int row = idx >> 4, c4 = (idx & 15) << 2;
            float4 rv = *(const float4*)(rg + (size_t)row * HK + c4);
            RKs[(c4 + 0) * 129 + row] = rv.x; RKs[(c4 + 1) * 129 + row] = rv.y;
            RKs[(c4 + 2) * 129 + row] = rv.z; RKs[(c4 + 3) * 129 + row] = rv.w;
        }
    }
    if (tid < 64) {
        rwbs[tid] = rwb[h * Kn + tid];
        rrbs[tid] = rrb[h * Kn + tid];
    }
    __syncthreads();

    // rank-1 bias terms
    if (tid < 64) {
        float s = 0.f;
#pragma unroll 8
        for (int k = 0; k < 64; k++) s = fmaf(rwbs[k], Ks[k * 65 + tid], s);
        c1s[tid] = s;
    } else if (tid < 64 + 127) {
        int ml = tid - 64;
        float s = 0.f;
#pragma unroll 8
        for (int k = 0; k < 64; k++) s = fmaf(rrbs[k], RKs[k * 129 + ml], s);
        c2s[ml] = s;
    }

    int tx = tid & 15, ty = tid >> 4;
    int mb = 60 + 4 * (tx - ty);           // in [0, 120]
    float acc[4][4] = {};
#pragma unroll 8
    for (int kk = 0; kk < 64; kk++) {
        float a[4], bk[4], r[7];
#pragma unroll
        for (int i = 0; i < 4; i++) a[i] = Qs[kk * 65 + ty * 4 + i];
#pragma unroll
        for (int j = 0; j < 4; j++) bk[j] = Ks[kk * 65 + tx * 4 + j];
#pragma unroll
        for (int u = 0; u < 7; u++) r[u] = RKs[kk * 129 + mb + u];
#pragma unroll
        for (int qi = 0; qi < 4; qi++)
#pragma unroll
            for (int jj = 0; jj < 4; jj++)
                acc[qi][jj] = fmaf(a[qi], bk[jj] + r[3 + jj - qi], acc[qi][jj]);
    }
    __syncthreads();

    float* out = g_logits + (size_t)z * Tn * Tn + (size_t)q0 * Tn + j0;
#pragma unroll
    for (int qi = 0; qi < 4; qi++)
#pragma unroll
        for (int jj = 0; jj < 4; jj++)
            out[(size_t)(ty * 4 + qi) * Tn + tx * 4 + jj] =
                acc[qi][jj] + c1s[tx * 4 + jj] + c2s[mb + 3 + jj - qi];
}

// ---------------- softmax (in place, one row per block) -----------------------
__global__ __launch_bounds__(128) void softmax_kernel() {
    __shared__ float red[4];
    size_t row = blockIdx.x;
    float4* pv = (float4*)(g_logits + row * Tn);
    int tid = threadIdx.x;
    float4 v[3];
#pragma unroll
    for (int u = 0; u < 3; u++) v[u] = pv[u * 128 + tid];
    float m = -1e30f;
#pragma unroll
    for (int u = 0; u < 3; u++)
        m = fmaxf(m, fmaxf(fmaxf(v[u].x, v[u].y), fmaxf(v[u].z, v[u].w)));
#pragma unroll
    for (int o = 16; o > 0; o >>= 1) m = fmaxf(m, __shfl_xor_sync(0xffffffffu, m, o));
    if ((tid & 31) == 0) red[tid >> 5] = m;
    __syncthreads();
    m = fmaxf(fmaxf(red[0], red[1]), fmaxf(red[2], red[3]));
    __syncthreads();
    float s = 0.f;
#pragma unroll
    for (int u = 0; u < 3; u++) {
        v[u].x = expf(v[u].x - m); v[u].y = expf(v[u].y - m);
        v[u].z = expf(v[u].z - m); v[u].w = expf(v[u].w - m);
        s += v[u].x + v[u].y + v[u].z + v[u].w;
    }
#pragma unroll
    for (int o = 16; o > 0; o >>= 1) s += __shfl_xor_sync(0xffffffffu, s, o);
    if ((tid & 31) == 0) red[tid >> 5] = s;
    __syncthreads();
    s = red[0] + red[1] + red[2] + red[3];
    float inv = 1.0f / s;
#pragma unroll
    for (int u = 0; u < 3; u++) {
        v[u].x *= inv; v[u].y *= inv; v[u].z *= inv; v[u].w *= inv;
        pv[u * 128 + tid] = v[u];
    }
}

// ---------------- host orchestration ------------------------------------------
extern "C" void kernel_launch(void* const* d_in, const int* in_sizes, int n_in,
                              void* d_out, int out_size)
{
    (void)in_sizes; (void)n_in; (void)out_size;
    const float* x    = (const float*)d_in[0];
    const float* Wq   = (const float*)d_in[1];
    const float* Wk   = (const float*)d_in[2];
    const float* Wv   = (const float*)d_in[3];
    const float* Wrk  = (const float*)d_in[4];
    const float* Wemb = (const float*)d_in[5];
    const float* rwb  = (const float*)d_in[6];
    const float* rrb  = (const float*)d_in[7];
    float* out = (float*)d_out;

    float *emb, *rk, *q, *k, *v, *logits, *att;
    cudaGetSymbolAddress((void**)&emb,    g_emb);
    cudaGetSymbolAddress((void**)&rk,     g_rk);
    cudaGetSymbolAddress((void**)&q,      g_q);
    cudaGetSymbolAddress((void**)&k,      g_k);
    cudaGetSymbolAddress((void**)&v,      g_v);
    cudaGetSymbolAddress((void**)&logits, g_logits);
    cudaGetSymbolAddress((void**)&att,    g_att);

    const int lg_smem = (64 * 65 * 2 + 64 * 129 + 64 + 127 + 64 + 64) * 4; // 67580 B
    cudaFuncSetAttribute(logits_kernel, cudaFuncAttributeMaxDynamicSharedMemorySize, lg_smem);

    // 1) positional features
    int n1 = Rn * 96;
    pos_fill<<<(n1 + 255) / 256, 256>>>();
    pos_max<<<1, 256>>>();
    pos_fin<<<(n1 + 255) / 256, 256>>>();

    // 2) r_k = emb @ Wrk   [3071,192]x[192,512]
    sgemm_kernel<<<dim3(4, 24, 1), 256>>>(emb, Wrk, rk, Rn, HK, 192, 192, HK, HK,
                                          1, 0, 0, 0, 0, 0, 0, 1.0f);
    // 3) q = (x @ Wq) * K^-0.5 ; k = x @ Wk ; v = x @ Wv
    sgemm_kernel<<<dim3(4, 24, 1), 256>>>(x, Wq, q, Bn * Tn, HK, Dn, Dn, HK, HK,
                                          1, 0, 0, 0, 0, 0, 0, 0.125f);
    sgemm_kernel<<<dim3(4, 24, 1), 256>>>(x, Wk, k, Bn * Tn, HK, Dn, Dn, HK, HK,
                                          1, 0, 0, 0, 0, 0, 0, 1.0f);
    sgemm_kernel<<<dim3(12, 24, 1), 256>>>(x, Wv, v, Bn * Tn, HV, Dn, Dn, HV, HV,
                                           1, 0, 0, 0, 0, 0, 0, 1.0f);
    // 4) fused logits (content + shifted rel + biases)
    logits_kernel<<<dim3(24, 24, Bn * Hn), 256, lg_smem>>>(rwb, rrb);

    // 5) softmax, in place
    softmax_kernel<<<Bn * Hn * Tn, 128>>>();

    // 6) att[b,q,h,v] = sum_j w[b,h,q,j] * v[b,j,h,v]  (batched over z=b*H+h)
    sgemm_kernel<<<dim3(2, 12, Bn * Hn), 256>>>(
        logits, v, att, Tn, Vn, Tn, Tn, HV, HV, Hn,
        (long)Hn * Tn * Tn, (long)Tn * Tn,
        (long)Tn * HV,      (long)Vn,
        (long)Tn * HV,      (long)Vn, 1.0f);

    // 7) out = att @ Wemb   [3072,1536]x[1536,1536]
    sgemm_kernel<<<dim3(12, 24, 1), 256>>>(att, Wemb, out, Bn * Tn, Dn, HV,
                                           HV, Dn, Dn, 1, 0, 0, 0, 0, 0, 0, 1.0f);
}

// round 2
// speedup vs baseline: 2.5066x; 2.5066x over previous
#include <cuda_runtime.h>
#include <math.h>

#define Bn 2
#define Tn 1536
#define Dn 1536
#define Hn 8
#define Kn 64
#define Vn 192
#define HK 512       // H*K
#define HV 1536      // H*V
#define Rn 3071      // 2T-1

// ---------------- scratch (device globals; no allocation allowed) -------------
__device__ float g_emb[(size_t)Rn * 192];
__device__ float g_gmax;
__device__ float g_rk[(size_t)Rn * HK];
__device__ float g_q[(size_t)Bn * Tn * HK];
__device__ float g_k[(size_t)Bn * Tn * HK];
__device__ float g_v[(size_t)Bn * Tn * HV];
__device__ float g_logits[(size_t)Bn * Hn * Tn * Tn];   // 151 MB
__device__ float g_att[(size_t)Bn * Tn * HV];

// ---------------- tf32 helpers -------------------------------------------------
__device__ __forceinline__ unsigned f2tf(float x) {
    unsigned u; asm("cvt.rna.tf32.f32 %0, %1;" : "=r"(u) : "f"(x)); return u;
}
__device__ __forceinline__ void mma8(float d[4], const unsigned a[4], const unsigned b[2]) {
    asm volatile(
        "mma.sync.aligned.m16n8k8.row.col.f32.tf32.tf32.f32 "
        "{%0,%1,%2,%3}, {%4,%5,%6,%7}, {%8,%9}, {%0,%1,%2,%3};"
        : "+f"(d[0]), "+f"(d[1]), "+f"(d[2]), "+f"(d[3])
        : "r"(a[0]), "r"(a[1]), "r"(a[2]), "r"(a[3]), "r"(b[0]), "r"(b[1]));
}

// ---------------- positional features ----------------------------------------
__global__ void pos_fill() {
    int idx = blockIdx.x * 256 + threadIdx.x;
    if (idx >= Rn * 96) return;
    int p = idx / 96, c = idx % 96;
    float ap = fabsf((float)(p - (Tn - 1)));
    float v;
    if (c < 32) {
        float max_range = log2f((float)Tn);
        float hl = exp2f(3.0f + (float)c * (max_range - 3.0f) / 31.0f);
        v = exp2f(-ap / hl);
    } else if (c < 64) {
        float w = exp2f((float)(c - 32 + 1)) - 1.0f;
        v = (w > ap) ? 1.0f : 0.0f;
    } else {
        int i = c - 64;
        float mean = 48.0f * (float)(i + 1);
        float conc = (mean / 24.0f) * (mean / 24.0f);
        float rate = mean * (1.0f / 576.0f);
        float lp = (conc - 1.0f) * logf(ap) - rate * ap
                   - (lgammaf(conc) - conc * logf(rate));
        v = expf(lp) + 1e-8f;
    }
    g_emb[(size_t)p * 192 + c] = v;
}

__global__ void pos_max() {
    __shared__ float red[256];
    int tid = threadIdx.x;
    float m = 0.0f;
    for (int idx = tid; idx < Rn * 32; idx += 256) {
        int p = idx >> 5, i = idx & 31;
        m = fmaxf(m, g_emb[(size_t)p * 192 + 64 + i]);
    }
    red[tid] = m;
    __syncthreads();
    for (int o = 128; o > 0; o >>= 1) {
        if (tid < o) red[tid] = fmaxf(red[tid], red[tid + o]);
        __syncthreads();
    }
    if (tid == 0) g_gmax = red[0];
}

__global__ void pos_fin() {
    int idx = blockIdx.x * 256 + threadIdx.x;
    if (idx >= Rn * 96) return;
    int p = idx / 96, c = idx % 96;
    float v = g_emb[(size_t)p * 192 + c];
    if (c >= 64) {
        v = v / g_gmax;
        g_emb[(size_t)p * 192 + c] = v;
    }
    float sgn = (p < Tn - 1) ? -1.0f : ((p > Tn - 1) ? 1.0f : 0.0f);
    g_emb[(size_t)p * 192 + 96 + c] = sgn * v;
}

// ---------------- tf32 tensor-core GEMM: C = alpha * A @ B --------------------
// 128x128x32 tiles, 256 thr (8 warps, warp tile 64x32 via m16n8k8).
// Requires Kd % 32 == 0, N % 4 == 0.
__global__ __launch_bounds__(256) void tgemm_kernel(
    const float* __restrict__ A, const float* __restrict__ B, float* __restrict__ C,
    int M, int N, int Kd, int lda, int ldb, int ldc, int Hdim,
    long sAb, long sAh, long sBb, long sBh, long sCb, long sCh, float alpha)
{
    int z = blockIdx.z;
    int bb = z / Hdim, hh = z % Hdim;
    A += (size_t)bb * sAb + (size_t)hh * sAh;
    B += (size_t)bb * sBb + (size_t)hh * sBh;
    C += (size_t)bb * sCb + (size_t)hh * sCh;

    __shared__ unsigned As[128 * 36];   // [m][k], ld 36 (conflict-free frags)
    __shared__ unsigned Bs[32 * 136];   // [k][n], ld 136

    int tid = threadIdx.x;
    int bm = blockIdx.y * 128, bn = blockIdx.x * 128;
    int w = tid >> 5, lane = tid & 31;
    int wm = w & 1, wn = w >> 1;        // warp grid 2(m) x 4(n)
    int lr = lane >> 2, lc = lane & 3;

    // global load mapping
    int arow0 = tid >> 3;               // + it*32
    int ac4   = (tid & 7) << 2;
    int bc4   = lane << 2;              // B col within tile (same for all its)
    bool bvalid = (bn + bc4) < N;
    bool avalid[4];
#pragma unroll
    for (int it = 0; it < 4; it++) avalid[it] = (bm + arow0 + it * 32) < M;

    float4 av[4], bv[4];
    const float4 z4 = make_float4(0.f, 0.f, 0.f, 0.f);
#pragma unroll
    for (int it = 0; it < 4; it++) {
        av[it] = avalid[it] ? *(const float4*)(A + (size_t)(bm + arow0 + it * 32) * lda + ac4) : z4;
        bv[it] = bvalid ? *(const float4*)(B + (size_t)(it * 8 + w) * ldb + bn + bc4) : z4;
    }

    float acc[4][4][4] = {};

    for (int k0 = 0; k0 < Kd; k0 += 32) {
#pragma unroll
        for (int it = 0; it < 4; it++) {
            unsigned* ap = As + (arow0 + it * 32) * 36 + ac4;
            ap[0] = f2tf(av[it].x); ap[1] = f2tf(av[it].y);
            ap[2] = f2tf(av[it].z); ap[3] = f2tf(av[it].w);
            unsigned* bp = Bs + (it * 8 + w) * 136 + bc4;
            bp[0] = f2tf(bv[it].x); bp[1] = f2tf(bv[it].y);
            bp[2] = f2tf(bv[it].z); bp[3] = f2tf(bv[it].w);
        }
        __syncthreads();
        if (k0 + 32 < Kd) {
#pragma unroll
            for (int it = 0; it < 4; it++) {
                av[it] = avalid[it] ? *(const float4*)(A + (size_t)(bm + arow0 + it * 32) * lda + (k0 + 32) + ac4) : z4;
                bv[it] = bvalid ? *(const float4*)(B + (size_t)(k0 + 32 + it * 8 + w) * ldb + bn + bc4) : z4;
            }
        }
#pragma unroll
        for (int s = 0; s < 4; s++) {
            int kb = s * 8;
            unsigned afr[4][4];
#pragma unroll
            for (int i = 0; i < 4; i++) {
                int r = wm * 64 + i * 16 + lr;
                afr[i][0] = As[r * 36 + kb + lc];
                afr[i][1] = As[(r + 8) * 36 + kb + lc];
                afr[i][2] = As[r * 36 + kb + 4 + lc];
                afr[i][3] = As[(r + 8) * 36 + kb + 4 + lc];
            }
            unsigned bfr[4][2];
#pragma unroll
            for (int j = 0; j < 4; j++) {
                int cc = wn * 32 + j * 8 + lr;
                bfr[j][0] = Bs[(kb + lc) * 136 + cc];
                bfr[j][1] = Bs[(kb + 4 + lc) * 136 + cc];
            }
#pragma unroll
            for (int i = 0; i < 4; i++)
#pragma unroll
                for (int j = 0; j < 4; j++)
                    mma8(acc[i][j], afr[i], bfr[j]);
        }
        __syncthreads();
    }

#pragma unroll
    for (int i = 0; i < 4; i++) {
        int r0 = bm + wm * 64 + i * 16 + lr;
#pragma unroll
        for (int j = 0; j < 4; j++) {
            int c0 = bn + wn * 32 + j * 8 + lc * 2;
            if (c0 < N) {
                if (r0 < M)
                    *(float2*)(C + (size_t)r0 * ldc + c0) =
                        make_float2(alpha * acc[i][j][0], alpha * acc[i][j][1]);
                if (r0 + 8 < M)
                    *(float2*)(C + (size_t)(r0 + 8) * ldc + c0) =
                        make_float2(alpha * acc[i][j][2], alpha * acc[i][j][3]);
            }
        }
    }
}

// ---------------- fused logits (tensor cores) ---------------------------------
// Per 64(q) x 64(j) tile:
//   rel[q][m]  = Q @ RKband^T   (64x128, band m = T-1+j0-q0-63 .. +63)
//   cont[q][j] = Q @ K^T        (64x64)
//   out[q][j]  = cont + rel[q][63+jl-ql] + c1[j] + c2[63+jl-ql]
__global__ __launch_bounds__(256) void logits_kernel(
    const float* __restrict__ rwb, const float* __restrict__ rrb)
{
    extern __shared__ unsigned sm[];
    unsigned* Qs  = sm;                 // [q][k]  64 x 68
    unsigned* Ks  = Qs + 64 * 68;       // [k][j]  64 x 72
    unsigned* RKs = Ks + 64 * 72;       // [k][m]  64 x 136 (later aliased: rel[q][m] ld 132)
    float* c1s = (float*)(RKs + 64 * 136);   // [64]
    float* c2s = c1s + 64;                   // [128]

    int z = blockIdx.z, b = z >> 3, h = z & 7;
    int q0 = blockIdx.y * 64, j0 = blockIdx.x * 64;
    int tid = threadIdx.x, w = tid >> 5, lane = tid & 31;
    int lr = lane >> 2, lc = lane & 3;

    const float* qg = g_q + (size_t)(b * Tn + q0) * HK + h * Kn;
    const float* kg = g_k + (size_t)(b * Tn + j0) * HK + h * Kn;
    int mbase = (Tn - 1) + j0 - q0 - 63;      // in [0, 2944]
    const float* rg = g_rk + (size_t)mbase * HK + h * Kn;

#pragma unroll
    for (int it = 0; it < 4; it++) {          // Q and K tiles (64x64 each)
        int f = it * 256 + tid;
        int row = f >> 4, c4 = (f & 15) << 2;
        float4 qv = *(const float4*)(qg + (size_t)row * HK + c4);
        float4 kv = *(const float4*)(kg + (size_t)row * HK + c4);
        unsigned* qp = Qs + row * 68 + c4;
        qp[0] = f2tf(qv.x); qp[1] = f2tf(qv.y); qp[2] = f2tf(qv.z); qp[3] = f2tf(qv.w);
        Ks[(c4 + 0) * 72 + row] = f2tf(kv.x);
        Ks[(c4 + 1) * 72 + row] = f2tf(kv.y);
        Ks[(c4 + 2) * 72 + row] = f2tf(kv.z);
        Ks[(c4 + 3) * 72 + row] = f2tf(kv.w);
    }
#pragma unroll
    for (int it = 0; it < 8; it++) {           // RK band: 127 rows
        int f = it * 256 + tid;
        if (f < 127 * 16) {
            int row = f >> 4, c4 = (f & 15) << 2;
            float4 rv = *(const float4*)(rg + (size_t)row * HK + c4);
            RKs[(c4 + 0) * 136 + row] = f2tf(rv.x);
            RKs[(c4 + 1) * 136 + row] = f2tf(rv.y);
            RKs[(c4 + 2) * 136 + row] = f2tf(rv.z);
            RKs[(c4 + 3) * 136 + row] = f2tf(rv.w);
        }
    }
    if (tid < 64) RKs[tid * 136 + 127] = 0;    // zero pad column m=127
    __syncthreads();

    // rank-1 bias terms (before RKs gets aliased)
    if (tid < 64) {
        float s = 0.f;
#pragma unroll 8
        for (int k = 0; k < 64; k++)
            s = fmaf(rwb[h * Kn + k], __uint_as_float(Ks[k * 72 + tid]), s);
        c1s[tid] = s;
    } else if (tid < 64 + 127) {
        int ml = tid - 64;
        float s = 0.f;
#pragma unroll 8
        for (int k = 0; k < 64; k++)
            s = fmaf(rrb[h * Kn + k], __uint_as_float(RKs[k * 136 + ml]), s);
        c2s[ml] = s;
    } else if (tid == 64 + 127) {
        c2s[127] = 0.f;
    }

    // fused MMA: shared A frag (16 q-rows per warp), rel (8 n-frags) + content (4 n-frags)
    int qw = (w >> 1) * 16;
    int mw = (w & 1) * 64;                     // rel col half
    int jw = (w & 1) * 32;                     // content col half
    float acc1[8][4] = {};
    float acc2[4][4] = {};
#pragma unroll
    for (int s = 0; s < 8; s++) {
        int kb = s * 8;
        unsigned afr[4];
        int r = qw + lr;
        afr[0] = Qs[r * 68 + kb + lc];
        afr[1] = Qs[(r + 8) * 68 + kb + lc];
        afr[2] = Qs[r * 68 + kb + 4 + lc];
        afr[3] = Qs[(r + 8) * 68 + kb + 4 + lc];
#pragma unroll
        for (int j = 0; j < 8; j++) {
            unsigned bfr[2];
            int cc = mw + j * 8 + lr;
            bfr[0] = RKs[(kb + lc) * 136 + cc];
            bfr[1] = RKs[(kb + 4 + lc) * 136 + cc];
            mma8(acc1[j], afr, bfr);
        }
#pragma unroll
        for (int j = 0; j < 4; j++) {
            unsigned bfr[2];
            int cc = jw + j * 8 + lr;
            bfr[0] = Ks[(kb + lc) * 72 + cc];
            bfr[1] = Ks[(kb + 4 + lc) * 72 + cc];
            mma8(acc2[j], afr, bfr);
        }
    }
    __syncthreads();

    // stage rel (+c2) into smem, aliased over RKs
    float* rel = (float*)RKs;                  // [q][m], ld 132 (8448 <= 8704 words)
#pragma unroll
    for (int j = 0; j < 8; j++) {
        int ml = mw + j * 8 + lc * 2;
        int r = qw + lr;
        *(float2*)&rel[r * 132 + ml] =
            make_float2(acc1[j][0] + c2s[ml], acc1[j][1] + c2s[ml + 1]);
        *(float2*)&rel[(r + 8) * 132 + ml] =
            make_float2(acc1[j][2] + c2s[ml], acc1[j][3] + c2s[ml + 1]);
    }
    __syncthreads();

    // final: content + shifted rel + c1
    float* out = g_logits + (size_t)z * Tn * Tn + (size_t)q0 * Tn + j0;
#pragma unroll
    for (int j = 0; j < 4; j++) {
        int jl = jw + j * 8 + lc * 2;
        int ql = qw + lr;
        {
            int ml = 63 + jl - ql;
            *(float2*)(out + (size_t)ql * Tn + jl) =
                make_float2(acc2[j][0] + rel[ql * 132 + ml] + c1s[jl],
                            acc2[j][1] + rel[ql * 132 + ml + 1] + c1s[jl + 1]);
        }
        {
            int ql2 = ql + 8;
            int ml = 63 + jl - ql2;
            *(float2*)(out + (size_t)ql2 * Tn + jl) =
                make_float2(acc2[j][2] + rel[ql2 * 132 + ml] + c1s[jl],
                            acc2[j][3] + rel[ql2 * 132 + ml + 1] + c1s[jl + 1]);
        }
    }
}

// ---------------- softmax (in place, one row per block) -----------------------
__global__ __launch_bounds__(128) void softmax_kernel() {
    __shared__ float red[4];
    size_t row = blockIdx.x;
    float4* pv = (float4*)(g_logits + row * Tn);
    int tid = threadIdx.x;
    float4 v[3];
#pragma unroll
    for (int u = 0; u < 3; u++) v[u] = pv[u * 128 + tid];
    float m = -1e30f;
#pragma unroll
    for (int u = 0; u < 3; u++)
        m = fmaxf(m, fmaxf(fmaxf(v[u].x, v[u].y), fmaxf(v[u].z, v[u].w)));
#pragma unroll
    for (int o = 16; o > 0; o >>= 1) m = fmaxf(m, __shfl_xor_sync(0xffffffffu, m, o));
    if ((tid & 31) == 0) red[tid >> 5] = m;
    __syncthreads();
    m = fmaxf(fmaxf(red[0], red[1]), fmaxf(red[2], red[3]));
    __syncthreads();
    float s = 0.f;
#pragma unroll
    for (int u = 0; u < 3; u++) {
        v[u].x = expf(v[u].x - m); v[u].y = expf(v[u].y - m);
        v[u].z = expf(v[u].z - m); v[u].w = expf(v[u].w - m);
        s += v[u].x + v[u].y + v[u].z + v[u].w;
    }
#pragma unroll
    for (int o = 16; o > 0; o >>= 1) s += __shfl_xor_sync(0xffffffffu, s, o);
    if ((tid & 31) == 0) red[tid >> 5] = s;
    __syncthreads();
    s = red[0] + red[1] + red[2] + red[3];
    float inv = 1.0f / s;
#pragma unroll
    for (int u = 0; u < 3; u++) {
        v[u].x *= inv; v[u].y *= inv; v[u].z *= inv; v[u].w *= inv;
        pv[u * 128 + tid] = v[u];
    }
}

// ---------------- host orchestration ------------------------------------------
extern "C" void kernel_launch(void* const* d_in, const int* in_sizes, int n_in,
                              void* d_out, int out_size)
{
    (void)in_sizes; (void)n_in; (void)out_size;
    const float* x    = (const float*)d_in[0];
    const float* Wq   = (const float*)d_in[1];
    const float* Wk   = (const float*)d_in[2];
    const float* Wv   = (const float*)d_in[3];
    const float* Wrk  = (const float*)d_in[4];
    const float* Wemb = (const float*)d_in[5];
    const float* rwb  = (const float*)d_in[6];
    const float* rrb  = (const float*)d_in[7];
    float* out = (float*)d_out;

    float *emb, *rk, *q, *k, *v, *logits, *att;
    cudaGetSymbolAddress((void**)&emb,    g_emb);
    cudaGetSymbolAddress((void**)&rk,     g_rk);
    cudaGetSymbolAddress((void**)&q,      g_q);
    cudaGetSymbolAddress((void**)&k,      g_k);
    cudaGetSymbolAddress((void**)&v,      g_v);
    cudaGetSymbolAddress((void**)&logits, g_logits);
    cudaGetSymbolAddress((void**)&att,    g_att);

    const int lg_smem = (64 * 68 + 64 * 72 + 64 * 136 + 64 + 128) * 4;  // 71424 B
    cudaFuncSetAttribute(logits_kernel, cudaFuncAttributeMaxDynamicSharedMemorySize, lg_smem);

    // 1) positional features
    int n1 = Rn * 96;
    pos_fill<<<(n1 + 255) / 256, 256>>>();
    pos_max<<<1, 256>>>();
    pos_fin<<<(n1 + 255) / 256, 256>>>();

    // 2) r_k = emb @ Wrk   [3071,192]x[192,512]
    tgemm_kernel<<<dim3(4, 24, 1), 256>>>(emb, Wrk, rk, Rn, HK, 192, 192, HK, HK,
                                          1, 0, 0, 0, 0, 0, 0, 1.0f);
    // 3) q = (x @ Wq) * K^-0.5 ; k = x @ Wk ; v = x @ Wv
    tgemm_kernel<<<dim3(4, 24, 1), 256>>>(x, Wq, q, Bn * Tn, HK, Dn, Dn, HK, HK,
                                          1, 0, 0, 0, 0, 0, 0, 0.125f);
    tgemm_kernel<<<dim3(4, 24, 1), 256>>>(x, Wk, k, Bn * Tn, HK, Dn, Dn, HK, HK,
                                          1, 0, 0, 0, 0, 0, 0, 1.0f);
    tgemm_kernel<<<dim3(12, 24, 1), 256>>>(x, Wv, v, Bn * Tn, HV, Dn, Dn, HV, HV,
                                           1, 0, 0, 0, 0, 0, 0, 1.0f);
    // 4) fused logits (content + shifted rel + biases)
    logits_kernel<<<dim3(24, 24, Bn * Hn), 256, lg_smem>>>(rwb, rrb);

    // 5) softmax, in place
    softmax_kernel<<<Bn * Hn * Tn, 128>>>();

    // 6) att[b,q,h,v] = sum_j w[b,h,q,j] * v[b,j,h,v]
    tgemm_kernel<<<dim3(2, 12, Bn * Hn), 256>>>(
        logits, v, att, Tn, Vn, Tn, Tn, HV, HV, Hn,
        (long)Hn * Tn * Tn, (long)Tn * Tn,
        (long)Tn * HV,      (long)Vn,
        (long)Tn * HV,      (long)Vn, 1.0f);

    // 7) out = att @ Wemb   [3072,1536]x[1536,1536]
    tgemm_kernel<<<dim3(12, 24, 1), 256>>>(att, Wemb, out, Bn * Tn, Dn, HV,
                                           HV, Dn, Dn, 1, 0, 0, 0, 0, 0, 0, 1.0f);
}

// round 3
// speedup vs baseline: 3.4652x; 1.3824x over previous
#include <cuda_runtime.h>
#include <math.h>

#define Bn 2
#define Tn 1536
#define Dn 1536
#define Hn 8
#define Kn 64
#define Vn 192
#define HK 512       // H*K
#define HV 1536      // H*V
#define Rn 3071      // 2T-1

// ---------------- scratch (device globals; no allocation allowed) -------------
__device__ float g_emb[(size_t)Rn * 192];
__device__ float g_gmax;
__device__ float g_rk[(size_t)Rn * HK];
__device__ float g_q[(size_t)Bn * Tn * HK];
__device__ float g_k[(size_t)Bn * Tn * HK];
__device__ float g_v[(size_t)Bn * Tn * HV];
__device__ float g_att[(size_t)Bn * Tn * HV];

// ---------------- tf32 helpers -------------------------------------------------
__device__ __forceinline__ unsigned f2tf(float x) {
    unsigned u; asm("cvt.rna.tf32.f32 %0, %1;" : "=r"(u) : "f"(x)); return u;
}
__device__ __forceinline__ void mma8(float d[4], const unsigned a[4], const unsigned b[2]) {
    asm volatile(
        "mma.sync.aligned.m16n8k8.row.col.f32.tf32.tf32.f32 "
        "{%0,%1,%2,%3}, {%4,%5,%6,%7}, {%8,%9}, {%0,%1,%2,%3};"
        : "+f"(d[0]), "+f"(d[1]), "+f"(d[2]), "+f"(d[3])
        : "r"(a[0]), "r"(a[1]), "r"(a[2]), "r"(a[3]), "r"(b[0]), "r"(b[1]));
}

// ---------------- positional features ----------------------------------------
__global__ void pos_fill() {
    int idx = blockIdx.x * 256 + threadIdx.x;
    if (idx >= Rn * 96) return;
    int p = idx / 96, c = idx % 96;
    float ap = fabsf((float)(p - (Tn - 1)));
    float v;
    if (c < 32) {
        float max_range = log2f((float)Tn);
        float hl = exp2f(3.0f + (float)c * (max_range - 3.0f) / 31.0f);
        v = exp2f(-ap / hl);
    } else if (c < 64) {
        float w = exp2f((float)(c - 32 + 1)) - 1.0f;
        v = (w > ap) ? 1.0f : 0.0f;
    } else {
        int i = c - 64;
        float mean = 48.0f * (float)(i + 1);
        float conc = (mean / 24.0f) * (mean / 24.0f);
        float rate = mean * (1.0f / 576.0f);
        float lp = (conc - 1.0f) * logf(ap) - rate * ap
                   - (lgammaf(conc) - conc * logf(rate));
        v = expf(lp) + 1e-8f;
    }
    g_emb[(size_t)p * 192 + c] = v;
}

__global__ void pos_max() {
    __shared__ float red[256];
    int tid = threadIdx.x;
    float m = 0.0f;
    for (int idx = tid; idx < Rn * 32; idx += 256) {
        int p = idx >> 5, i = idx & 31;
        m = fmaxf(m, g_emb[(size_t)p * 192 + 64 + i]);
    }
    red[tid] = m;
    __syncthreads();
    for (int o = 128; o > 0; o >>= 1) {
        if (tid < o) red[tid] = fmaxf(red[tid], red[tid + o]);
        __syncthreads();
    }
    if (tid == 0) g_gmax = red[0];
}

__global__ void pos_fin() {
    int idx = blockIdx.x * 256 + threadIdx.x;
    if (idx >= Rn * 96) return;
    int p = idx / 96, c = idx % 96;
    float v = g_emb[(size_t)p * 192 + c];
    if (c >= 64) {
        v = v / g_gmax;
        g_emb[(size_t)p * 192 + c] = v;
    }
    float sgn = (p < Tn - 1) ? -1.0f : ((p > Tn - 1) ? 1.0f : 0.0f);
    g_emb[(size_t)p * 192 + 96 + c] = sgn * v;
}

// ---------------- tf32 tensor-core GEMM: C = alpha * A @ B --------------------
__global__ __launch_bounds__(256) void tgemm_kernel(
    const float* __restrict__ A, const float* __restrict__ B, float* __restrict__ C,
    int M, int N, int Kd, int lda, int ldb, int ldc, int Hdim,
    long sAb, long sAh, long sBb, long sBh, long sCb, long sCh, float alpha)
{
    int z = blockIdx.z;
    int bb = z / Hdim, hh = z % Hdim;
    A += (size_t)bb * sAb + (size_t)hh * sAh;
    B += (size_t)bb * sBb + (size_t)hh * sBh;
    C += (size_t)bb * sCb + (size_t)hh * sCh;

    __shared__ unsigned As[128 * 36];   // [m][k], ld 36
    __shared__ unsigned Bs[32 * 136];   // [k][n], ld 136

    int tid = threadIdx.x;
    int bm = blockIdx.y * 128, bn = blockIdx.x * 128;
    int w = tid >> 5, lane = tid & 31;
    int wm = w & 1, wn = w >> 1;
    int lr = lane >> 2, lc = lane & 3;

    int arow0 = tid >> 3;
    int ac4   = (tid & 7) << 2;
    int bc4   = lane << 2;
    bool bvalid = (bn + bc4) < N;
    bool avalid[4];
#pragma unroll
    for (int it = 0; it < 4; it++) avalid[it] = (bm + arow0 + it * 32) < M;

    float4 av[4], bv[4];
    const float4 z4 = make_float4(0.f, 0.f, 0.f, 0.f);
#pragma unroll
    for (int it = 0; it < 4; it++) {
        av[it] = avalid[it] ? *(const float4*)(A + (size_t)(bm + arow0 + it * 32) * lda + ac4) : z4;
        bv[it] = bvalid ? *(const float4*)(B + (size_t)(it * 8 + w) * ldb + bn + bc4) : z4;
    }

    float acc[4][4][4] = {};

    for (int k0 = 0; k0 < Kd; k0 += 32) {
#pragma unroll
        for (int it = 0; it < 4; it++) {
            unsigned* ap = As + (arow0 + it * 32) * 36 + ac4;
            ap[0] = f2tf(av[it].x); ap[1] = f2tf(av[it].y);
            ap[2] = f2tf(av[it].z); ap[3] = f2tf(av[it].w);
            unsigned* bp = Bs + (it * 8 + w) * 136 + bc4;
            bp[0] = f2tf(bv[it].x); bp[1] = f2tf(bv[it].y);
            bp[2] = f2tf(bv[it].z); bp[3] = f2tf(bv[it].w);
        }
        __syncthreads();
        if (k0 + 32 < Kd) {
#pragma unroll
            for (int it = 0; it < 4; it++) {
                av[it] = avalid[it] ? *(const float4*)(A + (size_t)(bm + arow0 + it * 32) * lda + (k0 + 32) + ac4) : z4;
                bv[it] = bvalid ? *(const float4*)(B + (size_t)(k0 + 32 + it * 8 + w) * ldb + bn + bc4) : z4;
            }
        }
#pragma unroll
        for (int s = 0; s < 4; s++) {
            int kb = s * 8;
            unsigned afr[4][4];
#pragma unroll
            for (int i = 0; i < 4; i++) {
                int r = wm * 64 + i * 16 + lr;
                afr[i][0] = As[r * 36 + kb + lc];
                afr[i][1] = As[(r + 8) * 36 + kb + lc];
                afr[i][2] = As[r * 36 + kb + 4 + lc];
                afr[i][3] = As[(r + 8) * 36 + kb + 4 + lc];
            }
            unsigned bfr[4][2];
#pragma unroll
            for (int j = 0; j < 4; j++) {
                int cc = wn * 32 + j * 8 + lr;
                bfr[j][0] = Bs[(kb + lc) * 136 + cc];
                bfr[j][1] = Bs[(kb + 4 + lc) * 136 + cc];
            }
#pragma unroll
            for (int i = 0; i < 4; i++)
#pragma unroll
                for (int j = 0; j < 4; j++)
                    mma8(acc[i][j], afr[i], bfr[j]);
        }
        __syncthreads();
    }

#pragma unroll
    for (int i = 0; i < 4; i++) {
        int r0 = bm + wm * 64 + i * 16 + lr;
#pragma unroll
        for (int j = 0; j < 4; j++) {
            int c0 = bn + wn * 32 + j * 8 + lc * 2;
            if (c0 < N) {
                if (r0 < M)
                    *(float2*)(C + (size_t)r0 * ldc + c0) =
                        make_float2(alpha * acc[i][j][0], alpha * acc[i][j][1]);
                if (r0 + 8 < M)
                    *(float2*)(C + (size_t)(r0 + 8) * ldc + c0) =
                        make_float2(alpha * acc[i][j][2], alpha * acc[i][j][3]);
            }
        }
    }
}

// ---------------- fused flash attention with relative shift -------------------
// One block = (b,h, 64 q rows). Iterate 24 j-tiles of 64 with online softmax.
// logits[q,j] = (q+rwb).k[j] + (q+rrb).rk[T-1+j-q]; O = softmax(logits) @ V.
// Warp layout (8 warps): qgroup = (w>>1)*16 rows; half = w&1 splits n-dims.
#define LDK 68   // Ks2 [j][k], RKs2 [m][k]
#define LDV 200  // Vs  [j][v]
#define LDR 132  // rel [q][m] (aliases RKs2: 64*132 <= 128*68)
__global__ __launch_bounds__(256, 1) void flash_kernel(
    const float* __restrict__ rwb, const float* __restrict__ rrb)
{
    extern __shared__ unsigned smu[];
    unsigned* Ks2  = smu;                       // [64][LDK]  (n=j major)
    unsigned* RKs2 = smu + 64 * LDK;            // [128][LDK] (n=m major, row127=0)
    unsigned* Vs   = smu + 64 * LDK + 128 * LDK;// [64][LDV]
    float* smx = (float*)(Vs + 64 * LDV);       // [2][64] row max halves
    float* sms = smx + 128;                     // [2][64] row sum halves
    unsigned* Ps = Ks2;                         // alias: P tf32 [64][LDK]
    float*    rel = (float*)RKs2;               // alias: rel [64][LDR]

    int bh = blockIdx.y, b = bh >> 3, h = bh & 7;
    int q0 = blockIdx.x * 64;
    int tid = threadIdx.x, w = tid >> 5, lane = tid & 31;
    int lr = lane >> 2, lc = lane & 3;
    int qw = (w >> 1) * 16;          // warp's q-row group
    int nhalf = w & 1;               // splits rel cols (64), content cols (32), v cols (96)

    const float* qg = g_q + (size_t)(b * Tn + q0) * HK + h * Kn;

    // Q fragments with folded biases (loaded once)
    unsigned qc[8][4], qr[8][4];
#pragma unroll
    for (int s = 0; s < 8; s++) {
        int c = s * 8 + lc;
        float rw0 = rwb[h * Kn + c],     rr0 = rrb[h * Kn + c];
        float rw1 = rwb[h * Kn + c + 4], rr1 = rrb[h * Kn + c + 4];
        float q00 = qg[(size_t)(qw + lr) * HK + c];
        float q10 = qg[(size_t)(qw + 8 + lr) * HK + c];
        float q01 = qg[(size_t)(qw + lr) * HK + c + 4];
        float q11 = qg[(size_t)(qw + 8 + lr) * HK + c + 4];
        qc[s][0] = f2tf(q00 + rw0); qc[s][1] = f2tf(q10 + rw0);
        qc[s][2] = f2tf(q01 + rw1); qc[s][3] = f2tf(q11 + rw1);
        qr[s][0] = f2tf(q00 + rr0); qr[s][1] = f2tf(q10 + rr0);
        qr[s][2] = f2tf(q01 + rr1); qr[s][3] = f2tf(q11 + rr1);
    }

    float accO[12][4] = {};
    float m_lo = -1e30f, m_hi = -1e30f, l_lo = 0.f, l_hi = 0.f;

    for (int jt = 0; jt < 24; jt++) {
        int j0 = jt * 64;
        __syncthreads();   // previous iter's Ps/Vs/rel reads complete

        // ---- load K tile [64 j][64 k] row-major ----
        const float* kg = g_k + (size_t)(b * Tn + j0) * HK + h * Kn;
#pragma unroll
        for (int it = 0; it < 4; it++) {
            int f = it * 256 + tid;
            int row = f >> 4, c4 = (f & 15) << 2;
            float4 kv = *(const float4*)(kg + (size_t)row * HK + c4);
            unsigned* p = Ks2 + row * LDK + c4;
            p[0] = f2tf(kv.x); p[1] = f2tf(kv.y); p[2] = f2tf(kv.z); p[3] = f2tf(kv.w);
        }
        // ---- load RK band [127 m][64 k] row-major, zero row 127 ----
        int mbase = (Tn - 1) + j0 - q0 - 63;   // in [0, 2944]
        const float* rg = g_rk + (size_t)mbase * HK + h * Kn;
#pragma unroll
        for (int it = 0; it < 8; it++) {
            int f = it * 256 + tid;
            if (f < 127 * 16) {
                int row = f >> 4, c4 = (f & 15) << 2;
                float4 rv = *(const float4*)(rg + (size_t)row * HK + c4);
                unsigned* p = RKs2 + row * LDK + c4;
                p[0] = f2tf(rv.x); p[1] = f2tf(rv.y); p[2] = f2tf(rv.z); p[3] = f2tf(rv.w);
            }
        }
        if (tid < 16) *(uint4*)(RKs2 + 127 * LDK + tid * 4) = make_uint4(0, 0, 0, 0);
        // ---- load V tile [64 j][192 v] row-major ----
        const float* vg = g_v + (size_t)(b * Tn + j0) * HV + h * Vn;
#pragma unroll
        for (int it = 0; it < 12; it++) {
            int f = it * 256 + tid;
            int row = f / 48, c4 = (f % 48) << 2;
            float4 vv = *(const float4*)(vg + (size_t)row * HV + c4);
            unsigned* p = Vs + row * LDV + c4;
            p[0] = f2tf(vv.x); p[1] = f2tf(vv.y); p[2] = f2tf(vv.z); p[3] = f2tf(vv.w);
        }
        __syncthreads();

        // ---- MMAs: rel (64 cols per warp) + content (32 cols per warp) ----
        float acc1[8][4] = {};   // rel: cols nhalf*64 + jf*8
        float acc2[4][4] = {};   // content: cols nhalf*32 + jf*8
#pragma unroll
        for (int s = 0; s < 8; s++) {
            int kb = s * 8;
#pragma unroll
            for (int jf = 0; jf < 8; jf++) {
                int cc = nhalf * 64 + jf * 8 + lr;
                unsigned bfr[2];
                bfr[0] = RKs2[cc * LDK + kb + lc];
                bfr[1] = RKs2[cc * LDK + kb + 4 + lc];
                mma8(acc1[jf], qr[s], bfr);
            }
#pragma unroll
            for (int jf = 0; jf < 4; jf++) {
                int cc = nhalf * 32 + jf * 8 + lr;
                unsigned bfr[2];
                bfr[0] = Ks2[cc * LDK + kb + lc];
                bfr[1] = Ks2[cc * LDK + kb + 4 + lc];
                mma8(acc2[jf], qc[s], bfr);
            }
        }
        __syncthreads();   // Ks2/RKs2 frag reads done -> safe to alias

        // ---- stage rel into smem (aliased over RKs2) ----
#pragma unroll
        for (int jf = 0; jf < 8; jf++) {
            int ml = nhalf * 64 + jf * 8 + 2 * lc;
            *(float2*)&rel[(qw + lr) * LDR + ml]     = make_float2(acc1[jf][0], acc1[jf][1]);
            *(float2*)&rel[(qw + 8 + lr) * LDR + ml] = make_float2(acc1[jf][2], acc1[jf][3]);
        }
        __syncthreads();

        // ---- logits = content + shifted rel; row max ----
        float lg[4][4];
        float mx_lo = -1e30f, mx_hi = -1e30f;
#pragma unroll
        for (int jf = 0; jf < 4; jf++) {
            int jl = nhalf * 32 + jf * 8 + 2 * lc;
            int mlo = 63 + jl - (qw + lr);
            int mhi = mlo - 8;
            lg[jf][0] = acc2[jf][0] + rel[(qw + lr) * LDR + mlo];
            lg[jf][1] = acc2[jf][1] + rel[(qw + lr) * LDR + mlo + 1];
            lg[jf][2] = acc2[jf][2] + rel[(qw + 8 + lr) * LDR + mhi];
            lg[jf][3] = acc2[jf][3] + rel[(qw + 8 + lr) * LDR + mhi + 1];
            mx_lo = fmaxf(mx_lo, fmaxf(lg[jf][0], lg[jf][1]));
            mx_hi = fmaxf(mx_hi, fmaxf(lg[jf][2], lg[jf][3]));
        }
        // reduce over lc lanes (same row)
        mx_lo = fmaxf(mx_lo, __shfl_xor_sync(0xffffffffu, mx_lo, 1));
        mx_lo = fmaxf(mx_lo, __shfl_xor_sync(0xffffffffu, mx_lo, 2));
        mx_hi = fmaxf(mx_hi, __shfl_xor_sync(0xffffffffu, mx_hi, 1));
        mx_hi = fmaxf(mx_hi, __shfl_xor_sync(0xffffffffu, mx_hi, 2));
        if (lc == 0) {
            smx[nhalf * 64 + qw + lr] = mx_lo;
            smx[nhalf * 64 + qw + 8 + lr] = mx_hi;
        }
        __syncthreads();
        mx_lo = fmaxf(mx_lo, smx[(1 - nhalf) * 64 + qw + lr]);
        mx_hi = fmaxf(mx_hi, smx[(1 - nhalf) * 64 + qw + 8 + lr]);

        // ---- online softmax update ----
        float mn_lo = fmaxf(m_lo, mx_lo), mn_hi = fmaxf(m_hi, mx_hi);
        float sc_lo = expf(m_lo - mn_lo), sc_hi = expf(m_hi - mn_hi);
        m_lo = mn_lo; m_hi = mn_hi;
        float su_lo = 0.f, su_hi = 0.f;
        float pv[4][4];
#pragma unroll
        for (int jf = 0; jf < 4; jf++) {
            pv[jf][0] = expf(lg[jf][0] - mn_lo);
            pv[jf][1] = expf(lg[jf][1] - mn_lo);
            pv[jf][2] = expf(lg[jf][2] - mn_hi);
            pv[jf][3] = expf(lg[jf][3] - mn_hi);
            su_lo += pv[jf][0] + pv[jf][1];
            su_hi += pv[jf][2] + pv[jf][3];
        }
        su_lo += __shfl_xor_sync(0xffffffffu, su_lo, 1);
        su_lo += __shfl_xor_sync(0xffffffffu, su_lo, 2);
        su_hi += __shfl_xor_sync(0xffffffffu, su_hi, 1);
        su_hi += __shfl_xor_sync(0xffffffffu, su_hi, 2);
        if (lc == 0) {
            sms[nhalf * 64 + qw + lr] = su_lo;
            sms[nhalf * 64 + qw + 8 + lr] = su_hi;
        }
        // ---- stage P (tf32) into smem (aliased over Ks2) ----
#pragma unroll
        for (int jf = 0; jf < 4; jf++) {
            int jl = nhalf * 32 + jf * 8 + 2 * lc;
            *(uint2*)&Ps[(qw + lr) * LDK + jl] =
                make_uint2(f2tf(pv[jf][0]), f2tf(pv[jf][1]));
            *(uint2*)&Ps[(qw + 8 + lr) * LDK + jl] =
                make_uint2(f2tf(pv[jf][2]), f2tf(pv[jf][3]));
        }
        __syncthreads();
        l_lo = l_lo * sc_lo + su_lo + sms[(1 - nhalf) * 64 + qw + lr];
        l_hi = l_hi * sc_hi + su_hi + sms[(1 - nhalf) * 64 + qw + 8 + lr];

        // ---- rescale O accumulator, then O += P @ V ----
#pragma unroll
        for (int nf = 0; nf < 12; nf++) {
            accO[nf][0] *= sc_lo; accO[nf][1] *= sc_lo;
            accO[nf][2] *= sc_hi; accO[nf][3] *= sc_hi;
        }
#pragma unroll
        for (int s = 0; s < 8; s++) {
            int kb = s * 8;
            unsigned afr[4];
            afr[0] = Ps[(qw + lr) * LDK + kb + lc];
            afr[1] = Ps[(qw + 8 + lr) * LDK + kb + lc];
            afr[2] = Ps[(qw + lr) * LDK + kb + 4 + lc];
            afr[3] = Ps[(qw + 8 + lr) * LDK + kb + 4 + lc];
#pragma unroll
            for (int nf = 0; nf < 12; nf++) {
                int cc = nhalf * 96 + nf * 8 + lr;
                unsigned bfr[2];
                bfr[0] = Vs[(kb + lc) * LDV + cc];
                bfr[1] = Vs[(kb + 4 + lc) * LDV + cc];
                mma8(accO[nf], afr, bfr);
            }
        }
    }

    // ---- epilogue: normalize and write att[b, q, h*V + v] ----
    float il_lo = 1.0f / l_lo, il_hi = 1.0f / l_hi;
    float* og_lo = g_att + (size_t)(b * Tn + q0 + qw + lr) * HV + h * Vn;
    float* og_hi = og_lo + (size_t)8 * HV;
#pragma unroll
    for (int nf = 0; nf < 12; nf++) {
        int cc = nhalf * 96 + nf * 8 + 2 * lc;
        *(float2*)(og_lo + cc) = make_float2(accO[nf][0] * il_lo, accO[nf][1] * il_lo);
        *(float2*)(og_hi + cc) = make_float2(accO[nf][2] * il_hi, accO[nf][3] * il_hi);
    }
}

// ---------------- host orchestration ------------------------------------------
extern "C" void kernel_launch(void* const* d_in, const int* in_sizes, int n_in,
                              void* d_out, int out_size)
{
    (void)in_sizes; (void)n_in; (void)out_size;
    const float* x    = (const float*)d_in[0];
    const float* Wq   = (const float*)d_in[1];
    const float* Wk   = (const float*)d_in[2];
    const float* Wv   = (const float*)d_in[3];
    const float* Wrk  = (const float*)d_in[4];
    const float* Wemb = (const float*)d_in[5];
    const float* rwb  = (const float*)d_in[6];
    const float* rrb  = (const float*)d_in[7];
    float* out = (float*)d_out;

    float *emb, *rk, *q, *k, *v, *att;
    cudaGetSymbolAddress((void**)&emb, g_emb);
    cudaGetSymbolAddress((void**)&rk,  g_rk);
    cudaGetSymbolAddress((void**)&q,   g_q);
    cudaGetSymbolAddress((void**)&k,   g_k);
    cudaGetSymbolAddress((void**)&v,   g_v);
    cudaGetSymbolAddress((void**)&att, g_att);

    const int fa_smem = (64 * LDK + 128 * LDK + 64 * LDV + 256) * 4;  // 104448 B
    cudaFuncSetAttribute(flash_kernel, cudaFuncAttributeMaxDynamicSharedMemorySize, fa_smem);

    // 1) positional features
    int n1 = Rn * 96;
    pos_fill<<<(n1 + 255) / 256, 256>>>();
    pos_max<<<1, 256>>>();
    pos_fin<<<(n1 + 255) / 256, 256>>>();

    // 2) r_k = emb @ Wrk
    tgemm_kernel<<<dim3(4, 24, 1), 256>>>(emb, Wrk, rk, Rn, HK, 192, 192, HK, HK,
                                          1, 0, 0, 0, 0, 0, 0, 1.0f);
    // 3) q = (x @ Wq) * K^-0.5 ; k = x @ Wk ; v = x @ Wv
    tgemm_kernel<<<dim3(4, 24, 1), 256>>>(x, Wq, q, Bn * Tn, HK, Dn, Dn, HK, HK,
                                          1, 0, 0, 0, 0, 0, 0, 0.125f);
    tgemm_kernel<<<dim3(4, 24, 1), 256>>>(x, Wk, k, Bn * Tn, HK, Dn, Dn, HK, HK,
                                          1, 0, 0, 0, 0, 0, 0, 1.0f);
    tgemm_kernel<<<dim3(12, 24, 1), 256>>>(x, Wv, v, Bn * Tn, HV, Dn, Dn, HV, HV,
                                           1, 0, 0, 0, 0, 0, 0, 1.0f);

    // 4) fused attention (logits + relative shift + softmax + PV)
    flash_kernel<<<dim3(24, 16), 256, fa_smem>>>(rwb, rrb);

    // 5) out = att @ Wemb
    tgemm_kernel<<<dim3(12, 24, 1), 256>>>(att, Wemb, out, Bn * Tn, Dn, HV,
                                           HV, Dn, Dn, 1, 0, 0, 0, 0, 0, 0, 1.0f);
}